// round 13
// baseline (speedup 1.0000x reference)
#include <cuda_runtime.h>
#include <cstdint>

#define H_     4
#define F_     32
#define HF_    128
#define FIN_   128
#define EDGED_ 64
#define HID_   256
#define BMAX_  64
#define NMAX_  96000
#define EMAX_  600000

// ---------------- scratch (device globals; no allocation allowed) ----------
__device__ float    g_proj[NMAX_ * HF_];
__device__ float    g_skip[NMAX_ * HF_];        // skip + bias (written once by k1)
__device__ float    g_ss[NMAX_ * H_];
__device__ float    g_st[NMAX_ * H_];
__device__ float    g_scores[EMAX_ * H_];       // raw leaky-relu scores
__device__ float    g_asb[BMAX_ * HF_];
__device__ float    g_atb[BMAX_ * HF_];
__device__ float    g_waet[EDGED_ * BMAX_ * H_]; // folded edge matrix [p][b][h]
__device__ unsigned g_gmax;
// CSR scratch (both directions)
__device__ int      g_deg_trg[NMAX_];
__device__ int      g_deg_src[NMAX_];
__device__ int      g_off_trg[NMAX_ + 1];
__device__ int      g_off_src[NMAX_ + 1];
__device__ int      g_csr_trg[EMAX_];
__device__ int      g_csr_src[EMAX_];
__device__ int      g_blksum[2 * 512];

#define WAE_PADROW 65   // float4 row pad: bank16 = (j + b) % 8

// ordered-uint encoding of float (monotone)
__device__ __forceinline__ unsigned encf(float f) {
    unsigned u = __float_as_uint(f);
    return (u & 0x80000000u) ? ~u : (u | 0x80000000u);
}
__device__ __forceinline__ float decf(unsigned u) {
    return (u & 0x80000000u) ? __uint_as_float(u ^ 0x80000000u) : __uint_as_float(~u);
}

// ---- packed f32x2 helpers (sm_103a FFMA2 path, PTX-only) -------------------
__device__ __forceinline__ unsigned long long packdup(float x) {
    unsigned long long r;
    asm("mov.b64 %0, {%1, %1};" : "=l"(r) : "f"(x));
    return r;
}
__device__ __forceinline__ float2 unpk(unsigned long long v) {
    float2 r;
    asm("mov.b64 {%0, %1}, %2;" : "=f"(r.x), "=f"(r.y) : "l"(v));
    return r;
}
__device__ __forceinline__ void fma2(unsigned long long& acc, unsigned long long a,
                                     unsigned long long b) {
    asm("fma.rn.f32x2 %0, %1, %2, %0;" : "+l"(acc) : "l"(a), "l"(b));
}
__device__ __forceinline__ unsigned long long add2(unsigned long long a,
                                                   unsigned long long b) {
    unsigned long long r;
    asm("add.rn.f32x2 %0, %1, %2;" : "=l"(r) : "l"(a), "l"(b));
    return r;
}

// ---------------- K_init ----------------------------------------------------
__global__ void k_init(int N) {
    int i = blockIdx.x * blockDim.x + threadIdx.x;
    if (i == 0) g_gmax = 0u;
    if (i < N) { g_deg_trg[i] = 0; g_deg_src[i] = 0; }
}

// ---------------- K_hist ----------------------------------------------------
__global__ void k_hist(const int* __restrict__ ei, int E) {
    int e = blockIdx.x * blockDim.x + threadIdx.x;
    if (e >= E) return;
    atomicAdd(&g_deg_src[ei[e]], 1);
    atomicAdd(&g_deg_trg[ei[E + e]], 1);
}

// ---------------- parallel exclusive scan (3 phases, coalesced) --------------
__device__ __forceinline__ int block_incl_scan256(int v) {
    __shared__ int ws[8];
    int t = threadIdx.x, lane = t & 31, w = t >> 5;
    #pragma unroll
    for (int d = 1; d < 32; d <<= 1) {
        int o = __shfl_up_sync(~0u, v, d);
        if (lane >= d) v += o;
    }
    if (lane == 31) ws[w] = v;
    __syncthreads();
    if (w == 0) {
        int x = (lane < 8) ? ws[lane] : 0;
        #pragma unroll
        for (int d = 1; d < 8; d <<= 1) {
            int o = __shfl_up_sync(~0u, x, d);
            if (lane >= d) x += o;
        }
        if (lane < 8) ws[lane] = x;
    }
    __syncthreads();
    if (w > 0) v += ws[w - 1];
    return v;
}

__global__ __launch_bounds__(256) void k_scanA(int N) {
    int arr = blockIdx.y;
    const int* deg = arr ? g_deg_src : g_deg_trg;
    int i = blockIdx.x * 256 + threadIdx.x;
    int v = (i < N) ? deg[i] : 0;
    int incl = block_incl_scan256(v);
    if (threadIdx.x == 255) g_blksum[arr * 512 + blockIdx.x] = incl;
}

__global__ __launch_bounds__(512) void k_scanB(int nseg) {
    __shared__ int s[512];
    int t = threadIdx.x;
    for (int arr = 0; arr < 2; arr++) {
        int v = (t < nseg) ? g_blksum[arr * 512 + t] : 0;
        s[t] = v;
        __syncthreads();
        for (int d = 1; d < 512; d <<= 1) {
            int x = (t >= d) ? s[t - d] : 0;
            __syncthreads();
            s[t] += x;
            __syncthreads();
        }
        if (t < nseg) g_blksum[arr * 512 + t] = s[t] - v;   // exclusive
        __syncthreads();
    }
}

__global__ __launch_bounds__(256) void k_scanC(int N) {
    int arr = blockIdx.y;
    int* deg = arr ? g_deg_src : g_deg_trg;
    int* off = arr ? g_off_src : g_off_trg;
    int i = blockIdx.x * 256 + threadIdx.x;
    int v = (i < N) ? deg[i] : 0;
    int incl = block_incl_scan256(v);
    int base = g_blksum[arr * 512 + blockIdx.x];
    if (i < N) {
        off[i] = base + incl - v;
        deg[i] = 0;
        if (i == N - 1) off[N] = base + incl;
    }
}

// ---------------- K_fill -----------------------------------------------------
__global__ void k_fill(const int* __restrict__ ei, int E) {
    int e = blockIdx.x * blockDim.x + threadIdx.x;
    if (e >= E) return;
    int s = ei[e], tg = ei[E + e];
    int p1 = g_off_trg[tg] + atomicAdd(&g_deg_trg[tg], 1);
    g_csr_trg[p1] = e;
    int p2 = g_off_src[s] + atomicAdd(&g_deg_src[s], 1);
    g_csr_src[p2] = e;
}

// ---------------- K0: bridges + folded edge matrix ---------------------------
__global__ __launch_bounds__(128) void k0_batch(
    const float* __restrict__ ins,
    const float* __restrict__ Wsi, const float* __restrict__ bsi,
    const float* __restrict__ Wti, const float* __restrict__ bti,
    const float* __restrict__ Wei, const float* __restrict__ bei,
    const float* __restrict__ a_src, const float* __restrict__ a_trg,
    const float* __restrict__ a_edge, const float* __restrict__ W_edge)
{
    __shared__ float si[HID_];
    __shared__ float aeb[HF_];
    int b = blockIdx.x, t = threadIdx.x;
    si[t] = ins[b * HID_ + t];
    si[t + 128] = ins[b * HID_ + t + 128];
    __syncthreads();

    float s1 = bsi[t], s2 = bti[t], s3 = bei[t];
    #pragma unroll 4
    for (int k = 0; k < HID_; k++) {
        float iv = si[k];
        s1 += iv * Wsi[k * HF_ + t];
        s2 += iv * Wti[k * HF_ + t];
        s3 += iv * Wei[k * HF_ + t];
    }
    g_asb[b * HF_ + t] = a_src[t] * s1;
    g_atb[b * HF_ + t] = a_trg[t] * s2;
    aeb[t] = a_edge[t] * s3;
    __syncthreads();

    // waet[p][b][h], p = ((d&7)<<3)|(d>>3)  (k2 thread j owns d = 8j..8j+7;
    // its dd-th element d = 8j+dd lands at p = dd*8 + j)
    #pragma unroll
    for (int r = 0; r < 2; r++) {
        int idx = t + r * 128;
        int d = idx >> 2, h = idx & 3;
        float w = 0.f;
        #pragma unroll
        for (int f = 0; f < F_; f++) w += W_edge[d * HF_ + h * F_ + f] * aeb[h * F_ + f];
        int p = ((d & 7) << 3) | (d >> 3);
        g_waet[(p * BMAX_ + b) * H_ + h] = w;
    }
}

// ---------------- K1: fused GEMM, 128x128 tile, 8x8 microtile, FFMA2 --------
__global__ __launch_bounds__(256) void k1_gemm(
    const float* __restrict__ x, const float* __restrict__ Wp,
    const float* __restrict__ Wsk, const float* __restrict__ bias,
    int N, int mle)
{
    __shared__ float As[8][128];
    __shared__ float Bs[8][128];
    const float* W = (blockIdx.y == 0) ? Wp : Wsk;
    int t = threadIdx.x;
    int row0 = blockIdx.x * 128;
    int tx = t & 15, ty = t >> 4;

    unsigned long long acc2[8][4];
    #pragma unroll
    for (int i = 0; i < 8; i++)
        #pragma unroll
        for (int j = 0; j < 4; j++) acc2[i][j] = 0ull;

    int lr = t >> 1, lq = t & 1;
    int bk = t >> 5, bc = (t & 31) * 4;

    for (int k0 = 0; k0 < FIN_; k0 += 8) {
        int arow = row0 + lr;
        float4 av = make_float4(0.f, 0.f, 0.f, 0.f);
        if (arow < N) av = *(const float4*)(x + (size_t)arow * FIN_ + k0 + lq * 4);
        As[lq * 4 + 0][lr] = av.x; As[lq * 4 + 1][lr] = av.y;
        As[lq * 4 + 2][lr] = av.z; As[lq * 4 + 3][lr] = av.w;
        float4 bv = *(const float4*)(W + (size_t)(k0 + bk) * HF_ + bc);
        *(float4*)(&Bs[bk][bc]) = bv;
        __syncthreads();

        #pragma unroll
        for (int kk = 0; kk < 8; kk++) {
            float4 a0 = *(float4*)(&As[kk][ty * 8]);
            float4 a1 = *(float4*)(&As[kk][ty * 8 + 4]);
            ulonglong2 bp0 = *(const ulonglong2*)(&Bs[kk][tx * 8]);
            ulonglong2 bp1 = *(const ulonglong2*)(&Bs[kk][tx * 8 + 4]);
            unsigned long long bb[4] = {bp0.x, bp0.y, bp1.x, bp1.y};
            float a[8] = {a0.x, a0.y, a0.z, a0.w, a1.x, a1.y, a1.z, a1.w};
            #pragma unroll
            for (int i = 0; i < 8; i++) {
                unsigned long long aa = packdup(a[i]);
                fma2(acc2[i][0], aa, bb[0]);
                fma2(acc2[i][1], aa, bb[1]);
                fma2(acc2[i][2], aa, bb[2]);
                fma2(acc2[i][3], aa, bb[3]);
            }
        }
        __syncthreads();
    }

    if (blockIdx.y == 0) {
        int head = tx >> 2;
        #pragma unroll
        for (int i = 0; i < 8; i++) {
            int row = row0 + ty * 8 + i;
            int rc = row < N ? row : N - 1;
            int b = rc / mle;
            float2 c0 = unpk(acc2[i][0]);
            float2 c1 = unpk(acc2[i][1]);
            float2 c2 = unpk(acc2[i][2]);
            float2 c3 = unpk(acc2[i][3]);
            if (row < N) {
                float4 v0 = make_float4(c0.x, c0.y, c1.x, c1.y);
                float4 v1 = make_float4(c2.x, c2.y, c3.x, c3.y);
                *(float4*)(g_proj + (size_t)row * HF_ + tx * 8) = v0;
                *(float4*)(g_proj + (size_t)row * HF_ + tx * 8 + 4) = v1;
            }
            const float4* ab = (const float4*)(g_asb + b * HF_ + tx * 8);
            const float4* tb = (const float4*)(g_atb + b * HF_ + tx * 8);
            float4 ab0 = ab[0], ab1 = ab[1];
            float4 tb0 = tb[0], tb1 = tb[1];
            float s = c0.x * ab0.x + c0.y * ab0.y + c1.x * ab0.z + c1.y * ab0.w
                    + c2.x * ab1.x + c2.y * ab1.y + c3.x * ab1.z + c3.y * ab1.w;
            float u = c0.x * tb0.x + c0.y * tb0.y + c1.x * tb0.z + c1.y * tb0.w
                    + c2.x * tb1.x + c2.y * tb1.y + c3.x * tb1.z + c3.y * tb1.w;
            s += __shfl_xor_sync(~0u, s, 1);
            s += __shfl_xor_sync(~0u, s, 2);
            u += __shfl_xor_sync(~0u, u, 1);
            u += __shfl_xor_sync(~0u, u, 2);
            if ((tx & 3) == 0 && row < N) {
                g_ss[row * H_ + head] = s;
                g_st[row * H_ + head] = u;
            }
        }
    } else {
        const ulonglong2* bp = (const ulonglong2*)(bias + tx * 8);
        ulonglong2 bq0 = bp[0], bq1 = bp[1];
        unsigned long long bpk[4] = {bq0.x, bq0.y, bq1.x, bq1.y};
        #pragma unroll
        for (int i = 0; i < 8; i++) {
            int row = row0 + ty * 8 + i;
            if (row >= N) break;
            ulonglong2 w0, w1;
            w0.x = add2(acc2[i][0], bpk[0]);
            w0.y = add2(acc2[i][1], bpk[1]);
            w1.x = add2(acc2[i][2], bpk[2]);
            w1.y = add2(acc2[i][3], bpk[3]);
            *(ulonglong2*)(g_skip + (size_t)row * HF_ + tx * 8) = w0;
            *(ulonglong2*)(g_skip + (size_t)row * HF_ + tx * 8 + 4) = w1;
        }
    }
}

// ---------------- K2: per-edge scores, float4 smem table ---------------------
// Table in smem as float4[p][b] (h packed in float4), row pad 65.
// Thread j's dd-th element (d = 8j+dd) -> p = dd*8 + j ->
//   index = (dd*8 + j)*WAE_PADROW + b  (base j*WAE_PADROW + b, stride dd*8*PADROW)
// bank16 = (j + b) % 8 -> 8 consecutive 16B banks per edge.
__global__ __launch_bounds__(1024) void k2_edge_scores(
    const int* __restrict__ ei, const float* __restrict__ edges,
    const int* __restrict__ bids, int E)
{
    extern __shared__ float4 s_w4[];   // [64][65] float4
    int t = threadIdx.x;

    {
        const float4* g4 = (const float4*)g_waet;
        for (int i = t; i < EDGED_ * BMAX_; i += 1024) {
            int p = i >> 6, b = i & 63;
            s_w4[p * WAE_PADROW + b] = g4[i];
        }
    }
    __syncthreads();

    int lane = t & 31;
    int j = lane & 7;
    int esub = lane >> 3;
    int gw = (blockIdx.x * 1024 + t) >> 5;
    int nwarps = gridDim.x * 32;
    int G = (E + 3) >> 2;

    float m = -3.402823e38f;

    for (int g = gw; g < G; g += nwarps) {
        int e = g * 4 + esub;
        bool eok = e < E;
        int ec = eok ? e : E - 1;
        int b = bids[ec];

        const float4* er = (const float4*)(edges + (size_t)ec * EDGED_ + j * 8);
        float4 q0 = er[0], q1 = er[1];
        float ev[8] = {q0.x, q0.y, q0.z, q0.w, q1.x, q1.y, q1.z, q1.w};

        const float4* wp = s_w4 + j * WAE_PADROW + b;   // p = dd*8 + j
        float a0 = 0.f, a1 = 0.f, a2 = 0.f, a3 = 0.f;
        #pragma unroll
        for (int dd = 0; dd < 8; dd++) {
            float4 w = wp[dd * (8 * WAE_PADROW)];
            float evv = ev[dd];
            a0 += evv * w.x;
            a1 += evv * w.y;
            a2 += evv * w.z;
            a3 += evv * w.w;
        }
        #pragma unroll
        for (int mask = 1; mask <= 4; mask <<= 1) {
            a0 += __shfl_xor_sync(~0u, a0, mask);
            a1 += __shfl_xor_sync(~0u, a1, mask);
            a2 += __shfl_xor_sync(~0u, a2, mask);
            a3 += __shfl_xor_sync(~0u, a3, mask);
        }
        if (j == 0 && eok) {
            int src = ei[e], trg = ei[E + e];
            float4 sv = *(const float4*)(g_ss + src * H_);
            float4 tv = *(const float4*)(g_st + trg * H_);
            float4 s = make_float4(a0 + sv.x + tv.x, a1 + sv.y + tv.y,
                                   a2 + sv.z + tv.z, a3 + sv.w + tv.w);
            s.x = s.x > 0.f ? s.x : 0.2f * s.x;
            s.y = s.y > 0.f ? s.y : 0.2f * s.y;
            s.z = s.z > 0.f ? s.z : 0.2f * s.z;
            s.w = s.w > 0.f ? s.w : 0.2f * s.w;
            *((float4*)g_scores + e) = s;
            m = fmaxf(m, fmaxf(fmaxf(s.x, s.y), fmaxf(s.z, s.w)));
        }
    }

    __shared__ float wm[32];
    #pragma unroll
    for (int mask = 16; mask >= 1; mask >>= 1) m = fmaxf(m, __shfl_xor_sync(~0u, m, mask));
    if ((t & 31) == 0) wm[t >> 5] = m;
    __syncthreads();
    if (t < 32) {
        float v = wm[t];
        #pragma unroll
        for (int mask = 16; mask >= 1; mask >>= 1) v = fmaxf(v, __shfl_xor_sync(~0u, v, mask));
        if (t == 0) atomicMax(&g_gmax, encf(v));
    }
}

// ---------------- K3b: warp per (node, direction) + combined LayerNorm -------
__device__ __forceinline__ void gat_dir(const int* __restrict__ csr,
                                        const int* __restrict__ off,
                                        const int* __restrict__ oidx,
                                        int n, int lane, int h, float gm,
                                        float4& sum, float& den)
{
    int beg = off[n], end = off[n + 1];
    sum = make_float4(0.f, 0.f, 0.f, 0.f);
    den = 0.f;
    int eid = 0, other = 0;
    if (beg < end) { eid = csr[beg]; other = oidx[eid]; }
    for (int k = beg; k < end; k++) {
        float w = expf(g_scores[eid * H_ + h] - gm);
        float4 p = *((const float4*)g_proj + (size_t)other * 32 + lane);
        int kn = k + 1;
        if (kn < end) { eid = csr[kn]; other = oidx[eid]; }
        den += w;
        sum.x += w * p.x; sum.y += w * p.y;
        sum.z += w * p.z; sum.w += w * p.w;
    }
}

__global__ __launch_bounds__(256) void k3b_fused(
    const int* __restrict__ ei,
    const float* __restrict__ gamma, const float* __restrict__ beta,
    float* __restrict__ out, int N, int E)
{
    __shared__ float sh_s[8], sh_q[8];
    int wid = threadIdx.x >> 5, lane = threadIdx.x & 31;
    int gw = blockIdx.x * 8 + wid;
    int n = gw >> 1, dir = gw & 1;    // dir 0 = src_feats (first half), 1 = trg
    bool ok = n < N;
    int nc = ok ? n : N - 1;
    int h = lane >> 3;
    float gm = decf(g_gmax);

    const int* csr  = dir ? g_csr_trg : g_csr_src;
    const int* off  = dir ? g_off_trg : g_off_src;
    const int* oidx = dir ? ei : ei + E;

    float4 skip = *((const float4*)g_skip + (size_t)nc * 32 + lane);

    float4 sum; float den;
    gat_dir(csr, off, oidx, nc, lane, h, gm, sum, den);
    float inv = 1.f / (den + 1e-16f);
    float4 v = make_float4(skip.x + sum.x * inv, skip.y + sum.y * inv,
                           skip.z + sum.z * inv, skip.w + sum.w * inv);

    // partial LN stats for this half (128 values)
    float s = v.x + v.y + v.z + v.w;
    float q = v.x * v.x + v.y * v.y + v.z * v.z + v.w * v.w;
    #pragma unroll
    for (int mask = 16; mask >= 1; mask >>= 1) {
        s += __shfl_xor_sync(~0u, s, mask);
        q += __shfl_xor_sync(~0u, q, mask);
    }
    if (lane == 0) { sh_s[wid] = s; sh_q[wid] = q; }
    __syncthreads();
    int pw = wid ^ 1;   // partner warp handles the other direction of same node
    float st = sh_s[wid] + sh_s[pw];
    float qt = sh_q[wid] + sh_q[pw];

    float mu = st * (1.f / 256.f);
    float var = qt * (1.f / 256.f) - mu * mu;
    float r = rsqrtf(var + 1e-5f);
    float4 g1 = ((const float4*)gamma)[dir * 32 + lane];
    float4 be = ((const float4*)beta)[dir * 32 + lane];
    float4 o = make_float4((v.x - mu) * r * g1.x + be.x, (v.y - mu) * r * g1.y + be.y,
                           (v.z - mu) * r * g1.z + be.z, (v.w - mu) * r * g1.w + be.w);
    if (ok) ((float4*)out)[(size_t)n * 64 + dir * 32 + lane] = o;
}

// ---------------------------------------------------------------------------
static inline int cdiv(int a, int b) { return (a + b - 1) / b; }

extern "C" void kernel_launch(void* const* d_in, const int* in_sizes, int n_in,
                              void* d_out, int out_size)
{
    const float* x      = (const float*)d_in[0];
    const int*   ei     = (const int*)d_in[1];
    const float* edges  = (const float*)d_in[2];
    const float* ins    = (const float*)d_in[3];
    const int*   bids   = (const int*)d_in[4];
    const float* Wp     = (const float*)d_in[6];
    const float* We     = (const float*)d_in[7];
    const float* Wsi    = (const float*)d_in[8];
    const float* bsi    = (const float*)d_in[9];
    const float* Wti    = (const float*)d_in[10];
    const float* bti    = (const float*)d_in[11];
    const float* Wei    = (const float*)d_in[12];
    const float* bei    = (const float*)d_in[13];
    const float* a_src  = (const float*)d_in[14];
    const float* a_trg  = (const float*)d_in[15];
    const float* a_edge = (const float*)d_in[16];
    const float* bias   = (const float*)d_in[17];
    const float* Wsk    = (const float*)d_in[18];
    const float* gamma  = (const float*)d_in[19];
    const float* beta   = (const float*)d_in[20];

    int N = in_sizes[0] / FIN_;
    int E = in_sizes[2] / EDGED_;
    int B = in_sizes[3] / HID_;
    int mle = N / B;
    int nseg = cdiv(N, 256);

    const int k2_smem = EDGED_ * WAE_PADROW * (int)sizeof(float4);  // 66560 B
    cudaFuncSetAttribute(k2_edge_scores,
                         cudaFuncAttributeMaxDynamicSharedMemorySize, k2_smem);

    // CSR build (parallel 3-phase scan)
    k_init<<<cdiv(N, 256), 256>>>(N);
    k_hist<<<cdiv(E, 256), 256>>>(ei, E);
    {
        dim3 g1(nseg, 2);
        k_scanA<<<g1, 256>>>(N);
        k_scanB<<<1, 512>>>(nseg);
        k_scanC<<<g1, 256>>>(N);
    }
    k_fill<<<cdiv(E, 256), 256>>>(ei, E);

    k0_batch<<<B, 128>>>(ins, Wsi, bsi, Wti, bti, Wei, bei, a_src, a_trg, a_edge, We);
    {
        dim3 grid(cdiv(N, 128), 2);
        k1_gemm<<<grid, 256>>>(x, Wp, Wsk, bias, N, mle);
    }
    k2_edge_scores<<<296, 1024, k2_smem>>>(ei, edges, bids, E);
    k3b_fused<<<cdiv(2 * N * 32, 256), 256>>>(ei, gamma, beta, (float*)d_out, N, E);
}

// round 14
// speedup vs baseline: 1.1495x; 1.1495x over previous
#include <cuda_runtime.h>
#include <cstdint>

#define H_     4
#define F_     32
#define HF_    128
#define FIN_   128
#define EDGED_ 64
#define HID_   256
#define BMAX_  64
#define NMAX_  96000
#define EMAX_  600000

// ---------------- scratch (device globals; no allocation allowed) ----------
__device__ float    g_proj[NMAX_ * HF_];
__device__ float    g_skip[NMAX_ * HF_];        // skip + bias (written once by k1)
__device__ float    g_ss[NMAX_ * H_];
__device__ float    g_st[NMAX_ * H_];
__device__ float    g_scores[EMAX_ * H_];       // scores -> exp(scores - max)
__device__ float    g_asb[BMAX_ * HF_];
__device__ float    g_atb[BMAX_ * HF_];
__device__ float    g_waet[EDGED_ * BMAX_ * H_]; // folded edge matrix [p][b][h]
__device__ unsigned g_gmax;
// CSR scratch (both directions)
__device__ int      g_deg_trg[NMAX_];
__device__ int      g_deg_src[NMAX_];
__device__ int      g_off_trg[NMAX_ + 1];
__device__ int      g_off_src[NMAX_ + 1];
__device__ int      g_csr_trg[EMAX_];
__device__ int      g_csr_src[EMAX_];
__device__ int      g_blksum[2 * 512];

#define WAE_PADROW 65   // float4 row pad: bank16 = (j + b) % 8

// ordered-uint encoding of float (monotone)
__device__ __forceinline__ unsigned encf(float f) {
    unsigned u = __float_as_uint(f);
    return (u & 0x80000000u) ? ~u : (u | 0x80000000u);
}
__device__ __forceinline__ float decf(unsigned u) {
    return (u & 0x80000000u) ? __uint_as_float(u ^ 0x80000000u) : __uint_as_float(~u);
}

// ---- packed f32x2 helpers (sm_103a FFMA2 path, PTX-only) -------------------
__device__ __forceinline__ unsigned long long packdup(float x) {
    unsigned long long r;
    asm("mov.b64 %0, {%1, %1};" : "=l"(r) : "f"(x));
    return r;
}
__device__ __forceinline__ float2 unpk(unsigned long long v) {
    float2 r;
    asm("mov.b64 {%0, %1}, %2;" : "=f"(r.x), "=f"(r.y) : "l"(v));
    return r;
}
__device__ __forceinline__ void fma2(unsigned long long& acc, unsigned long long a,
                                     unsigned long long b) {
    asm("fma.rn.f32x2 %0, %1, %2, %0;" : "+l"(acc) : "l"(a), "l"(b));
}
__device__ __forceinline__ unsigned long long add2(unsigned long long a,
                                                   unsigned long long b) {
    unsigned long long r;
    asm("add.rn.f32x2 %0, %1, %2;" : "=l"(r) : "l"(a), "l"(b));
    return r;
}

// ---------------- K_init ----------------------------------------------------
__global__ void k_init(int N) {
    int i = blockIdx.x * blockDim.x + threadIdx.x;
    if (i == 0) g_gmax = 0u;
    if (i < N) { g_deg_trg[i] = 0; g_deg_src[i] = 0; }
}

// ---------------- K_hist ----------------------------------------------------
__global__ void k_hist(const int* __restrict__ ei, int E) {
    int e = blockIdx.x * blockDim.x + threadIdx.x;
    if (e >= E) return;
    atomicAdd(&g_deg_src[ei[e]], 1);
    atomicAdd(&g_deg_trg[ei[E + e]], 1);
}

// ---------------- parallel exclusive scan (3 phases, coalesced) --------------
__device__ __forceinline__ int block_incl_scan256(int v) {
    __shared__ int ws[8];
    int t = threadIdx.x, lane = t & 31, w = t >> 5;
    #pragma unroll
    for (int d = 1; d < 32; d <<= 1) {
        int o = __shfl_up_sync(~0u, v, d);
        if (lane >= d) v += o;
    }
    if (lane == 31) ws[w] = v;
    __syncthreads();
    if (w == 0) {
        int x = (lane < 8) ? ws[lane] : 0;
        #pragma unroll
        for (int d = 1; d < 8; d <<= 1) {
            int o = __shfl_up_sync(~0u, x, d);
            if (lane >= d) x += o;
        }
        if (lane < 8) ws[lane] = x;
    }
    __syncthreads();
    if (w > 0) v += ws[w - 1];
    return v;
}

__global__ __launch_bounds__(256) void k_scanA(int N) {
    int arr = blockIdx.y;
    const int* deg = arr ? g_deg_src : g_deg_trg;
    int i = blockIdx.x * 256 + threadIdx.x;
    int v = (i < N) ? deg[i] : 0;
    int incl = block_incl_scan256(v);
    if (threadIdx.x == 255) g_blksum[arr * 512 + blockIdx.x] = incl;
}

__global__ __launch_bounds__(512) void k_scanB(int nseg) {
    __shared__ int s[512];
    int t = threadIdx.x;
    for (int arr = 0; arr < 2; arr++) {
        int v = (t < nseg) ? g_blksum[arr * 512 + t] : 0;
        s[t] = v;
        __syncthreads();
        for (int d = 1; d < 512; d <<= 1) {
            int x = (t >= d) ? s[t - d] : 0;
            __syncthreads();
            s[t] += x;
            __syncthreads();
        }
        if (t < nseg) g_blksum[arr * 512 + t] = s[t] - v;   // exclusive
        __syncthreads();
    }
}

__global__ __launch_bounds__(256) void k_scanC(int N) {
    int arr = blockIdx.y;
    int* deg = arr ? g_deg_src : g_deg_trg;
    int* off = arr ? g_off_src : g_off_trg;
    int i = blockIdx.x * 256 + threadIdx.x;
    int v = (i < N) ? deg[i] : 0;
    int incl = block_incl_scan256(v);
    int base = g_blksum[arr * 512 + blockIdx.x];
    if (i < N) {
        off[i] = base + incl - v;
        deg[i] = 0;
        if (i == N - 1) off[N] = base + incl;
    }
}

// ---------------- K_fill -----------------------------------------------------
__global__ void k_fill(const int* __restrict__ ei, int E) {
    int e = blockIdx.x * blockDim.x + threadIdx.x;
    if (e >= E) return;
    int s = ei[e], tg = ei[E + e];
    int p1 = g_off_trg[tg] + atomicAdd(&g_deg_trg[tg], 1);
    g_csr_trg[p1] = e;
    int p2 = g_off_src[s] + atomicAdd(&g_deg_src[s], 1);
    g_csr_src[p2] = e;
}

// ---------------- K0: bridges + folded edge matrix ---------------------------
__global__ __launch_bounds__(128) void k0_batch(
    const float* __restrict__ ins,
    const float* __restrict__ Wsi, const float* __restrict__ bsi,
    const float* __restrict__ Wti, const float* __restrict__ bti,
    const float* __restrict__ Wei, const float* __restrict__ bei,
    const float* __restrict__ a_src, const float* __restrict__ a_trg,
    const float* __restrict__ a_edge, const float* __restrict__ W_edge)
{
    __shared__ float si[HID_];
    __shared__ float aeb[HF_];
    int b = blockIdx.x, t = threadIdx.x;
    si[t] = ins[b * HID_ + t];
    si[t + 128] = ins[b * HID_ + t + 128];
    __syncthreads();

    float s1 = bsi[t], s2 = bti[t], s3 = bei[t];
    #pragma unroll 4
    for (int k = 0; k < HID_; k++) {
        float iv = si[k];
        s1 += iv * Wsi[k * HF_ + t];
        s2 += iv * Wti[k * HF_ + t];
        s3 += iv * Wei[k * HF_ + t];
    }
    g_asb[b * HF_ + t] = a_src[t] * s1;
    g_atb[b * HF_ + t] = a_trg[t] * s2;
    aeb[t] = a_edge[t] * s3;
    __syncthreads();

    // waet[p][b][h], p = ((d&7)<<3)|(d>>3)  (k2 thread j owns d = 8j..8j+7;
    // its dd-th element d = 8j+dd lands at p = dd*8 + j)
    #pragma unroll
    for (int r = 0; r < 2; r++) {
        int idx = t + r * 128;
        int d = idx >> 2, h = idx & 3;
        float w = 0.f;
        #pragma unroll
        for (int f = 0; f < F_; f++) w += W_edge[d * HF_ + h * F_ + f] * aeb[h * F_ + f];
        int p = ((d & 7) << 3) | (d >> 3);
        g_waet[(p * BMAX_ + b) * H_ + h] = w;
    }
}

// ---------------- K1: fused GEMM, 128x128 tile, 8x8 microtile, FFMA2 --------
__global__ __launch_bounds__(256) void k1_gemm(
    const float* __restrict__ x, const float* __restrict__ Wp,
    const float* __restrict__ Wsk, const float* __restrict__ bias,
    int N, int mle)
{
    __shared__ float As[8][128];
    __shared__ float Bs[8][128];
    const float* W = (blockIdx.y == 0) ? Wp : Wsk;
    int t = threadIdx.x;
    int row0 = blockIdx.x * 128;
    int tx = t & 15, ty = t >> 4;

    unsigned long long acc2[8][4];
    #pragma unroll
    for (int i = 0; i < 8; i++)
        #pragma unroll
        for (int j = 0; j < 4; j++) acc2[i][j] = 0ull;

    int lr = t >> 1, lq = t & 1;
    int bk = t >> 5, bc = (t & 31) * 4;

    for (int k0 = 0; k0 < FIN_; k0 += 8) {
        int arow = row0 + lr;
        float4 av = make_float4(0.f, 0.f, 0.f, 0.f);
        if (arow < N) av = *(const float4*)(x + (size_t)arow * FIN_ + k0 + lq * 4);
        As[lq * 4 + 0][lr] = av.x; As[lq * 4 + 1][lr] = av.y;
        As[lq * 4 + 2][lr] = av.z; As[lq * 4 + 3][lr] = av.w;
        float4 bv = *(const float4*)(W + (size_t)(k0 + bk) * HF_ + bc);
        *(float4*)(&Bs[bk][bc]) = bv;
        __syncthreads();

        #pragma unroll
        for (int kk = 0; kk < 8; kk++) {
            float4 a0 = *(float4*)(&As[kk][ty * 8]);
            float4 a1 = *(float4*)(&As[kk][ty * 8 + 4]);
            ulonglong2 bp0 = *(const ulonglong2*)(&Bs[kk][tx * 8]);
            ulonglong2 bp1 = *(const ulonglong2*)(&Bs[kk][tx * 8 + 4]);
            unsigned long long bb[4] = {bp0.x, bp0.y, bp1.x, bp1.y};
            float a[8] = {a0.x, a0.y, a0.z, a0.w, a1.x, a1.y, a1.z, a1.w};
            #pragma unroll
            for (int i = 0; i < 8; i++) {
                unsigned long long aa = packdup(a[i]);
                fma2(acc2[i][0], aa, bb[0]);
                fma2(acc2[i][1], aa, bb[1]);
                fma2(acc2[i][2], aa, bb[2]);
                fma2(acc2[i][3], aa, bb[3]);
            }
        }
        __syncthreads();
    }

    if (blockIdx.y == 0) {
        int head = tx >> 2;
        #pragma unroll
        for (int i = 0; i < 8; i++) {
            int row = row0 + ty * 8 + i;
            int rc = row < N ? row : N - 1;
            int b = rc / mle;
            float2 c0 = unpk(acc2[i][0]);
            float2 c1 = unpk(acc2[i][1]);
            float2 c2 = unpk(acc2[i][2]);
            float2 c3 = unpk(acc2[i][3]);
            if (row < N) {
                float4 v0 = make_float4(c0.x, c0.y, c1.x, c1.y);
                float4 v1 = make_float4(c2.x, c2.y, c3.x, c3.y);
                *(float4*)(g_proj + (size_t)row * HF_ + tx * 8) = v0;
                *(float4*)(g_proj + (size_t)row * HF_ + tx * 8 + 4) = v1;
            }
            const float4* ab = (const float4*)(g_asb + b * HF_ + tx * 8);
            const float4* tb = (const float4*)(g_atb + b * HF_ + tx * 8);
            float4 ab0 = ab[0], ab1 = ab[1];
            float4 tb0 = tb[0], tb1 = tb[1];
            float s = c0.x * ab0.x + c0.y * ab0.y + c1.x * ab0.z + c1.y * ab0.w
                    + c2.x * ab1.x + c2.y * ab1.y + c3.x * ab1.z + c3.y * ab1.w;
            float u = c0.x * tb0.x + c0.y * tb0.y + c1.x * tb0.z + c1.y * tb0.w
                    + c2.x * tb1.x + c2.y * tb1.y + c3.x * tb1.z + c3.y * tb1.w;
            s += __shfl_xor_sync(~0u, s, 1);
            s += __shfl_xor_sync(~0u, s, 2);
            u += __shfl_xor_sync(~0u, u, 1);
            u += __shfl_xor_sync(~0u, u, 2);
            if ((tx & 3) == 0 && row < N) {
                g_ss[row * H_ + head] = s;
                g_st[row * H_ + head] = u;
            }
        }
    } else {
        const ulonglong2* bp = (const ulonglong2*)(bias + tx * 8);
        ulonglong2 bq0 = bp[0], bq1 = bp[1];
        unsigned long long bpk[4] = {bq0.x, bq0.y, bq1.x, bq1.y};
        #pragma unroll
        for (int i = 0; i < 8; i++) {
            int row = row0 + ty * 8 + i;
            if (row >= N) break;
            ulonglong2 w0, w1;
            w0.x = add2(acc2[i][0], bpk[0]);
            w0.y = add2(acc2[i][1], bpk[1]);
            w1.x = add2(acc2[i][2], bpk[2]);
            w1.y = add2(acc2[i][3], bpk[3]);
            *(ulonglong2*)(g_skip + (size_t)row * HF_ + tx * 8) = w0;
            *(ulonglong2*)(g_skip + (size_t)row * HF_ + tx * 8 + 4) = w1;
        }
    }
}

// ---------------- K2: per-edge scores, float4 smem table ---------------------
// Table in smem as float4[p][b] (h packed in float4), row pad 65.
// Thread j's dd-th element (d = 8j+dd) -> p = dd*8 + j ->
//   index = (dd*8 + j)*WAE_PADROW + b  (base j*WAE_PADROW + b, stride dd*8*PADROW)
// bank16 = (j + b) % 8 -> 8 consecutive 16B banks per edge.
__global__ __launch_bounds__(1024) void k2_edge_scores(
    const int* __restrict__ ei, const float* __restrict__ edges,
    const int* __restrict__ bids, int E)
{
    extern __shared__ float4 s_w4[];   // [64][65] float4
    int t = threadIdx.x;

    {
        const float4* g4 = (const float4*)g_waet;
        for (int i = t; i < EDGED_ * BMAX_; i += 1024) {
            int p = i >> 6, b = i & 63;
            s_w4[p * WAE_PADROW + b] = g4[i];
        }
    }
    __syncthreads();

    int lane = t & 31;
    int j = lane & 7;
    int esub = lane >> 3;
    int gw = (blockIdx.x * 1024 + t) >> 5;
    int nwarps = gridDim.x * 32;
    int G = (E + 3) >> 2;

    float m = -3.402823e38f;

    for (int g = gw; g < G; g += nwarps) {
        int e = g * 4 + esub;
        bool eok = e < E;
        int ec = eok ? e : E - 1;
        int b = bids[ec];

        const float4* er = (const float4*)(edges + (size_t)ec * EDGED_ + j * 8);
        float4 q0 = er[0], q1 = er[1];
        float ev[8] = {q0.x, q0.y, q0.z, q0.w, q1.x, q1.y, q1.z, q1.w};

        const float4* wp = s_w4 + j * WAE_PADROW + b;   // p = dd*8 + j
        float a0 = 0.f, a1 = 0.f, a2 = 0.f, a3 = 0.f;
        #pragma unroll
        for (int dd = 0; dd < 8; dd++) {
            float4 w = wp[dd * (8 * WAE_PADROW)];
            float evv = ev[dd];
            a0 += evv * w.x;
            a1 += evv * w.y;
            a2 += evv * w.z;
            a3 += evv * w.w;
        }
        #pragma unroll
        for (int mask = 1; mask <= 4; mask <<= 1) {
            a0 += __shfl_xor_sync(~0u, a0, mask);
            a1 += __shfl_xor_sync(~0u, a1, mask);
            a2 += __shfl_xor_sync(~0u, a2, mask);
            a3 += __shfl_xor_sync(~0u, a3, mask);
        }
        if (j == 0 && eok) {
            int src = ei[e], trg = ei[E + e];
            float4 sv = *(const float4*)(g_ss + src * H_);
            float4 tv = *(const float4*)(g_st + trg * H_);
            float4 s = make_float4(a0 + sv.x + tv.x, a1 + sv.y + tv.y,
                                   a2 + sv.z + tv.z, a3 + sv.w + tv.w);
            s.x = s.x > 0.f ? s.x : 0.2f * s.x;
            s.y = s.y > 0.f ? s.y : 0.2f * s.y;
            s.z = s.z > 0.f ? s.z : 0.2f * s.z;
            s.w = s.w > 0.f ? s.w : 0.2f * s.w;
            *((float4*)g_scores + e) = s;
            m = fmaxf(m, fmaxf(fmaxf(s.x, s.y), fmaxf(s.z, s.w)));
        }
    }

    __shared__ float wm[32];
    #pragma unroll
    for (int mask = 16; mask >= 1; mask >>= 1) m = fmaxf(m, __shfl_xor_sync(~0u, m, mask));
    if ((t & 31) == 0) wm[t >> 5] = m;
    __syncthreads();
    if (t < 32) {
        float v = wm[t];
        #pragma unroll
        for (int mask = 16; mask >= 1; mask >>= 1) v = fmaxf(v, __shfl_xor_sync(~0u, v, mask));
        if (t == 0) atomicMax(&g_gmax, encf(v));
    }
}

// ---------------- K3a: elementwise exp(score - max) --------------------------
__global__ void k3a_exp(int E) {
    int e = blockIdx.x * blockDim.x + threadIdx.x;
    if (e >= E) return;
    float gm = decf(g_gmax);
    float4 s = *((float4*)g_scores + e);
    float4 ex = make_float4(expf(s.x - gm), expf(s.y - gm), expf(s.z - gm), expf(s.w - gm));
    *((float4*)g_scores + e) = ex;
}

// ---------------- K3b: fused dual-direction gather + LayerNorm ---------------
__device__ __forceinline__ void gat_dir(const int* __restrict__ csr,
                                        const int* __restrict__ off,
                                        const int* __restrict__ oidx,
                                        int n, int lane, int h,
                                        float4& sum, float& den)
{
    int beg = off[n], end = off[n + 1];
    sum = make_float4(0.f, 0.f, 0.f, 0.f);
    den = 0.f;
    int eid = 0, other = 0;
    if (beg < end) { eid = csr[beg]; other = oidx[eid]; }
    for (int k = beg; k < end; k++) {
        float w = g_scores[eid * H_ + h];
        float4 p = *((const float4*)g_proj + (size_t)other * 32 + lane);
        int kn = k + 1;
        if (kn < end) { eid = csr[kn]; other = oidx[eid]; }
        den += w;
        sum.x += w * p.x; sum.y += w * p.y;
        sum.z += w * p.z; sum.w += w * p.w;
    }
}

__global__ __launch_bounds__(256) void k3b_fused(
    const int* __restrict__ ei,
    const float* __restrict__ gamma, const float* __restrict__ beta,
    float* __restrict__ out, int N, int E)
{
    int n = (int)((blockIdx.x * 256 + threadIdx.x) >> 5);
    int lane = threadIdx.x & 31;
    if (n >= N) return;
    int h = lane >> 3;

    float4 skip = *((const float4*)g_skip + (size_t)n * 32 + lane);

    // src_feats: aggregated at src, lifts proj[trg] (other = ei[E+e])
    float4 ssum; float sden;
    gat_dir(g_csr_src, g_off_src, ei + E, n, lane, h, ssum, sden);
    float sinv = 1.f / (sden + 1e-16f);
    float4 a = make_float4(skip.x + ssum.x * sinv, skip.y + ssum.y * sinv,
                           skip.z + ssum.z * sinv, skip.w + ssum.w * sinv);

    // trg_feats: aggregated at trg, lifts proj[src] (other = ei[e])
    float4 tsum; float tden;
    gat_dir(g_csr_trg, g_off_trg, ei, n, lane, h, tsum, tden);
    float tinv = 1.f / (tden + 1e-16f);
    float4 b = make_float4(skip.x + tsum.x * tinv, skip.y + tsum.y * tinv,
                           skip.z + tsum.z * tinv, skip.w + tsum.w * tinv);

    // LayerNorm over concat([src_feats, trg_feats]) = 256 values
    float s = a.x + a.y + a.z + a.w + b.x + b.y + b.z + b.w;
    float q = a.x * a.x + a.y * a.y + a.z * a.z + a.w * a.w +
              b.x * b.x + b.y * b.y + b.z * b.z + b.w * b.w;
    #pragma unroll
    for (int mask = 16; mask >= 1; mask >>= 1) {
        s += __shfl_xor_sync(~0u, s, mask);
        q += __shfl_xor_sync(~0u, q, mask);
    }
    float mu = s * (1.f / 256.f);
    float var = q * (1.f / 256.f) - mu * mu;
    float r = rsqrtf(var + 1e-5f);
    float4 g1 = ((const float4*)gamma)[lane];
    float4 be1 = ((const float4*)beta)[lane];
    float4 g2 = ((const float4*)gamma)[32 + lane];
    float4 be2 = ((const float4*)beta)[32 + lane];
    float4 o1 = make_float4((a.x - mu) * r * g1.x + be1.x, (a.y - mu) * r * g1.y + be1.y,
                            (a.z - mu) * r * g1.z + be1.z, (a.w - mu) * r * g1.w + be1.w);
    float4 o2 = make_float4((b.x - mu) * r * g2.x + be2.x, (b.y - mu) * r * g2.y + be2.y,
                            (b.z - mu) * r * g2.z + be2.z, (b.w - mu) * r * g2.w + be2.w);
    ((float4*)out)[(size_t)n * 64 + lane] = o1;
    ((float4*)out)[(size_t)n * 64 + 32 + lane] = o2;
}

// ---------------------------------------------------------------------------
static inline int cdiv(int a, int b) { return (a + b - 1) / b; }

extern "C" void kernel_launch(void* const* d_in, const int* in_sizes, int n_in,
                              void* d_out, int out_size)
{
    const float* x      = (const float*)d_in[0];
    const int*   ei     = (const int*)d_in[1];
    const float* edges  = (const float*)d_in[2];
    const float* ins    = (const float*)d_in[3];
    const int*   bids   = (const int*)d_in[4];
    const float* Wp     = (const float*)d_in[6];
    const float* We     = (const float*)d_in[7];
    const float* Wsi    = (const float*)d_in[8];
    const float* bsi    = (const float*)d_in[9];
    const float* Wti    = (const float*)d_in[10];
    const float* bti    = (const float*)d_in[11];
    const float* Wei    = (const float*)d_in[12];
    const float* bei    = (const float*)d_in[13];
    const float* a_src  = (const float*)d_in[14];
    const float* a_trg  = (const float*)d_in[15];
    const float* a_edge = (const float*)d_in[16];
    const float* bias   = (const float*)d_in[17];
    const float* Wsk    = (const float*)d_in[18];
    const float* gamma  = (const float*)d_in[19];
    const float* beta   = (const float*)d_in[20];

    int N = in_sizes[0] / FIN_;
    int E = in_sizes[2] / EDGED_;
    int B = in_sizes[3] / HID_;
    int mle = N / B;
    int nseg = cdiv(N, 256);

    const int k2_smem = EDGED_ * WAE_PADROW * (int)sizeof(float4);  // 66560 B
    cudaFuncSetAttribute(k2_edge_scores,
                         cudaFuncAttributeMaxDynamicSharedMemorySize, k2_smem);

    // CSR build (parallel 3-phase scan)
    k_init<<<cdiv(N, 256), 256>>>(N);
    k_hist<<<cdiv(E, 256), 256>>>(ei, E);
    {
        dim3 g1(nseg, 2);
        k_scanA<<<g1, 256>>>(N);
        k_scanB<<<1, 512>>>(nseg);
        k_scanC<<<g1, 256>>>(N);
    }
    k_fill<<<cdiv(E, 256), 256>>>(ei, E);

    k0_batch<<<B, 128>>>(ins, Wsi, bsi, Wti, bti, Wei, bei, a_src, a_trg, a_edge, We);
    {
        dim3 grid(cdiv(N, 128), 2);
        k1_gemm<<<grid, 256>>>(x, Wp, Wsk, bias, N, mle);
    }
    k2_edge_scores<<<296, 1024, k2_smem>>>(ei, edges, bids, E);
    k3a_exp<<<cdiv(E, 256), 256>>>(E);
    k3b_fused<<<cdiv(N * 32, 256), 256>>>(ei, gamma, beta, (float*)d_out, N, E);
}

// round 15
// speedup vs baseline: 1.2549x; 1.0917x over previous
#include <cuda_runtime.h>
#include <cstdint>

#define H_     4
#define F_     32
#define HF_    128
#define FIN_   128
#define EDGED_ 64
#define HID_   256
#define BMAX_  64
#define NMAX_  96000
#define EMAX_  600000

// ---------------- scratch (device globals; no allocation allowed) ----------
__device__ float    g_proj[NMAX_ * HF_];
__device__ float    g_skip[NMAX_ * HF_];        // skip + bias (written once by k1)
__device__ float    g_ss[NMAX_ * H_];
__device__ float    g_st[NMAX_ * H_];
__device__ float    g_scores[EMAX_ * H_];       // scores -> exp(scores - max)
__device__ float    g_asb[BMAX_ * HF_];
__device__ float    g_atb[BMAX_ * HF_];
__device__ float    g_waet[EDGED_ * BMAX_ * H_]; // folded edge matrix [p][b][h]
__device__ unsigned g_gmax;
// CSR scratch (both directions); payload = {edge id, other endpoint}
__device__ int      g_deg_trg[NMAX_];
__device__ int      g_deg_src[NMAX_];
__device__ int      g_off_trg[NMAX_ + 1];
__device__ int      g_off_src[NMAX_ + 1];
__device__ int2     g_csr_trg[EMAX_];
__device__ int2     g_csr_src[EMAX_];
__device__ int      g_blksum[2 * 512];

#define WAE_PADROW 65   // float4 row pad: bank16 = (j + b) % 8

// ordered-uint encoding of float (monotone)
__device__ __forceinline__ unsigned encf(float f) {
    unsigned u = __float_as_uint(f);
    return (u & 0x80000000u) ? ~u : (u | 0x80000000u);
}
__device__ __forceinline__ float decf(unsigned u) {
    return (u & 0x80000000u) ? __uint_as_float(u ^ 0x80000000u) : __uint_as_float(~u);
}

// ---- packed f32x2 helpers (sm_103a FFMA2 path, PTX-only) -------------------
__device__ __forceinline__ unsigned long long packdup(float x) {
    unsigned long long r;
    asm("mov.b64 %0, {%1, %1};" : "=l"(r) : "f"(x));
    return r;
}
__device__ __forceinline__ float2 unpk(unsigned long long v) {
    float2 r;
    asm("mov.b64 {%0, %1}, %2;" : "=f"(r.x), "=f"(r.y) : "l"(v));
    return r;
}
__device__ __forceinline__ void fma2(unsigned long long& acc, unsigned long long a,
                                     unsigned long long b) {
    asm("fma.rn.f32x2 %0, %1, %2, %0;" : "+l"(acc) : "l"(a), "l"(b));
}
__device__ __forceinline__ unsigned long long add2(unsigned long long a,
                                                   unsigned long long b) {
    unsigned long long r;
    asm("add.rn.f32x2 %0, %1, %2;" : "=l"(r) : "l"(a), "l"(b));
    return r;
}

// ---------------- K_init ----------------------------------------------------
__global__ void k_init(int N) {
    int i = blockIdx.x * blockDim.x + threadIdx.x;
    if (i == 0) g_gmax = 0u;
    if (i < N) { g_deg_trg[i] = 0; g_deg_src[i] = 0; }
}

// ---------------- K_hist ----------------------------------------------------
__global__ void k_hist(const int* __restrict__ ei, int E) {
    int e = blockIdx.x * blockDim.x + threadIdx.x;
    if (e >= E) return;
    atomicAdd(&g_deg_src[ei[e]], 1);
    atomicAdd(&g_deg_trg[ei[E + e]], 1);
}

// ---------------- parallel exclusive scan (3 phases, coalesced) --------------
__device__ __forceinline__ int block_incl_scan256(int v) {
    __shared__ int ws[8];
    int t = threadIdx.x, lane = t & 31, w = t >> 5;
    #pragma unroll
    for (int d = 1; d < 32; d <<= 1) {
        int o = __shfl_up_sync(~0u, v, d);
        if (lane >= d) v += o;
    }
    if (lane == 31) ws[w] = v;
    __syncthreads();
    if (w == 0) {
        int x = (lane < 8) ? ws[lane] : 0;
        #pragma unroll
        for (int d = 1; d < 8; d <<= 1) {
            int o = __shfl_up_sync(~0u, x, d);
            if (lane >= d) x += o;
        }
        if (lane < 8) ws[lane] = x;
    }
    __syncthreads();
    if (w > 0) v += ws[w - 1];
    return v;
}

__global__ __launch_bounds__(256) void k_scanA(int N) {
    int arr = blockIdx.y;
    const int* deg = arr ? g_deg_src : g_deg_trg;
    int i = blockIdx.x * 256 + threadIdx.x;
    int v = (i < N) ? deg[i] : 0;
    int incl = block_incl_scan256(v);
    if (threadIdx.x == 255) g_blksum[arr * 512 + blockIdx.x] = incl;
}

__global__ __launch_bounds__(512) void k_scanB(int nseg) {
    __shared__ int s[512];
    int t = threadIdx.x;
    for (int arr = 0; arr < 2; arr++) {
        int v = (t < nseg) ? g_blksum[arr * 512 + t] : 0;
        s[t] = v;
        __syncthreads();
        for (int d = 1; d < 512; d <<= 1) {
            int x = (t >= d) ? s[t - d] : 0;
            __syncthreads();
            s[t] += x;
            __syncthreads();
        }
        if (t < nseg) g_blksum[arr * 512 + t] = s[t] - v;   // exclusive
        __syncthreads();
    }
}

__global__ __launch_bounds__(256) void k_scanC(int N) {
    int arr = blockIdx.y;
    int* deg = arr ? g_deg_src : g_deg_trg;
    int* off = arr ? g_off_src : g_off_trg;
    int i = blockIdx.x * 256 + threadIdx.x;
    int v = (i < N) ? deg[i] : 0;
    int incl = block_incl_scan256(v);
    int base = g_blksum[arr * 512 + blockIdx.x];
    if (i < N) {
        off[i] = base + incl - v;
        deg[i] = 0;
        if (i == N - 1) off[N] = base + incl;
    }
}

// ---------------- K_fill: CSR payload carries the other endpoint -------------
__global__ void k_fill(const int* __restrict__ ei, int E) {
    int e = blockIdx.x * blockDim.x + threadIdx.x;
    if (e >= E) return;
    int s = ei[e], tg = ei[E + e];
    int p1 = g_off_trg[tg] + atomicAdd(&g_deg_trg[tg], 1);
    g_csr_trg[p1] = make_int2(e, s);     // aggregated at trg -> lifts proj[src]
    int p2 = g_off_src[s] + atomicAdd(&g_deg_src[s], 1);
    g_csr_src[p2] = make_int2(e, tg);    // aggregated at src -> lifts proj[trg]
}

// ---------------- K0: bridges + folded edge matrix ---------------------------
__global__ __launch_bounds__(128) void k0_batch(
    const float* __restrict__ ins,
    const float* __restrict__ Wsi, const float* __restrict__ bsi,
    const float* __restrict__ Wti, const float* __restrict__ bti,
    const float* __restrict__ Wei, const float* __restrict__ bei,
    const float* __restrict__ a_src, const float* __restrict__ a_trg,
    const float* __restrict__ a_edge, const float* __restrict__ W_edge)
{
    __shared__ float si[HID_];
    __shared__ float aeb[HF_];
    int b = blockIdx.x, t = threadIdx.x;
    si[t] = ins[b * HID_ + t];
    si[t + 128] = ins[b * HID_ + t + 128];
    __syncthreads();

    float s1 = bsi[t], s2 = bti[t], s3 = bei[t];
    #pragma unroll 4
    for (int k = 0; k < HID_; k++) {
        float iv = si[k];
        s1 += iv * Wsi[k * HF_ + t];
        s2 += iv * Wti[k * HF_ + t];
        s3 += iv * Wei[k * HF_ + t];
    }
    g_asb[b * HF_ + t] = a_src[t] * s1;
    g_atb[b * HF_ + t] = a_trg[t] * s2;
    aeb[t] = a_edge[t] * s3;
    __syncthreads();

    // waet[p][b][h], p = ((d&7)<<3)|(d>>3)
    #pragma unroll
    for (int r = 0; r < 2; r++) {
        int idx = t + r * 128;
        int d = idx >> 2, h = idx & 3;
        float w = 0.f;
        #pragma unroll
        for (int f = 0; f < F_; f++) w += W_edge[d * HF_ + h * F_ + f] * aeb[h * F_ + f];
        int p = ((d & 7) << 3) | (d >> 3);
        g_waet[(p * BMAX_ + b) * H_ + h] = w;
    }
}

// ---------------- K1: fused GEMM, 128x128, 8x8 microtile, double-buffered ----
__global__ __launch_bounds__(256) void k1_gemm(
    const float* __restrict__ x, const float* __restrict__ Wp,
    const float* __restrict__ Wsk, const float* __restrict__ bias,
    int N, int mle)
{
    __shared__ float As[2][8][128];
    __shared__ float Bs[2][8][128];
    const float* W = (blockIdx.y == 0) ? Wp : Wsk;
    int t = threadIdx.x;
    int row0 = blockIdx.x * 128;
    int tx = t & 15, ty = t >> 4;

    unsigned long long acc2[8][4];
    #pragma unroll
    for (int i = 0; i < 8; i++)
        #pragma unroll
        for (int j = 0; j < 4; j++) acc2[i][j] = 0ull;

    int lr = t >> 1, lq = t & 1;
    int bk = t >> 5, bc = (t & 31) * 4;
    int arow = row0 + lr;
    bool arow_ok = arow < N;
    const float* xrow = x + (size_t)(arow_ok ? arow : 0) * FIN_ + lq * 4;

    // preload tile 0
    {
        float4 av = arow_ok ? *(const float4*)(xrow) : make_float4(0.f, 0.f, 0.f, 0.f);
        As[0][lq * 4 + 0][lr] = av.x; As[0][lq * 4 + 1][lr] = av.y;
        As[0][lq * 4 + 2][lr] = av.z; As[0][lq * 4 + 3][lr] = av.w;
        float4 bv = *(const float4*)(W + (size_t)bk * HF_ + bc);
        *(float4*)(&Bs[0][bk][bc]) = bv;
    }
    __syncthreads();

    #pragma unroll
    for (int it = 0; it < 16; it++) {
        int cur = it & 1;
        float4 av2, bv2;
        bool more = it < 15;
        if (more) {
            int k0 = (it + 1) * 8;
            av2 = arow_ok ? *(const float4*)(xrow + k0) : make_float4(0.f, 0.f, 0.f, 0.f);
            bv2 = *(const float4*)(W + (size_t)(k0 + bk) * HF_ + bc);
        }

        #pragma unroll
        for (int kk = 0; kk < 8; kk++) {
            float4 a0 = *(float4*)(&As[cur][kk][ty * 8]);
            float4 a1 = *(float4*)(&As[cur][kk][ty * 8 + 4]);
            ulonglong2 bp0 = *(const ulonglong2*)(&Bs[cur][kk][tx * 8]);
            ulonglong2 bp1 = *(const ulonglong2*)(&Bs[cur][kk][tx * 8 + 4]);
            unsigned long long bb[4] = {bp0.x, bp0.y, bp1.x, bp1.y};
            float a[8] = {a0.x, a0.y, a0.z, a0.w, a1.x, a1.y, a1.z, a1.w};
            #pragma unroll
            for (int i = 0; i < 8; i++) {
                unsigned long long aa = packdup(a[i]);
                fma2(acc2[i][0], aa, bb[0]);
                fma2(acc2[i][1], aa, bb[1]);
                fma2(acc2[i][2], aa, bb[2]);
                fma2(acc2[i][3], aa, bb[3]);
            }
        }

        if (more) {
            int nxt = cur ^ 1;
            As[nxt][lq * 4 + 0][lr] = av2.x; As[nxt][lq * 4 + 1][lr] = av2.y;
            As[nxt][lq * 4 + 2][lr] = av2.z; As[nxt][lq * 4 + 3][lr] = av2.w;
            *(float4*)(&Bs[nxt][bk][bc]) = bv2;
        }
        __syncthreads();
    }

    if (blockIdx.y == 0) {
        int head = tx >> 2;
        #pragma unroll
        for (int i = 0; i < 8; i++) {
            int row = row0 + ty * 8 + i;
            int rc = row < N ? row : N - 1;
            int b = rc / mle;
            float2 c0 = unpk(acc2[i][0]);
            float2 c1 = unpk(acc2[i][1]);
            float2 c2 = unpk(acc2[i][2]);
            float2 c3 = unpk(acc2[i][3]);
            if (row < N) {
                float4 v0 = make_float4(c0.x, c0.y, c1.x, c1.y);
                float4 v1 = make_float4(c2.x, c2.y, c3.x, c3.y);
                *(float4*)(g_proj + (size_t)row * HF_ + tx * 8) = v0;
                *(float4*)(g_proj + (size_t)row * HF_ + tx * 8 + 4) = v1;
            }
            const float4* ab = (const float4*)(g_asb + b * HF_ + tx * 8);
            const float4* tb = (const float4*)(g_atb + b * HF_ + tx * 8);
            float4 ab0 = ab[0], ab1 = ab[1];
            float4 tb0 = tb[0], tb1 = tb[1];
            float s = c0.x * ab0.x + c0.y * ab0.y + c1.x * ab0.z + c1.y * ab0.w
                    + c2.x * ab1.x + c2.y * ab1.y + c3.x * ab1.z + c3.y * ab1.w;
            float u = c0.x * tb0.x + c0.y * tb0.y + c1.x * tb0.z + c1.y * tb0.w
                    + c2.x * tb1.x + c2.y * tb1.y + c3.x * tb1.z + c3.y * tb1.w;
            s += __shfl_xor_sync(~0u, s, 1);
            s += __shfl_xor_sync(~0u, s, 2);
            u += __shfl_xor_sync(~0u, u, 1);
            u += __shfl_xor_sync(~0u, u, 2);
            if ((tx & 3) == 0 && row < N) {
                g_ss[row * H_ + head] = s;
                g_st[row * H_ + head] = u;
            }
        }
    } else {
        const ulonglong2* bp = (const ulonglong2*)(bias + tx * 8);
        ulonglong2 bq0 = bp[0], bq1 = bp[1];
        unsigned long long bpk[4] = {bq0.x, bq0.y, bq1.x, bq1.y};
        #pragma unroll
        for (int i = 0; i < 8; i++) {
            int row = row0 + ty * 8 + i;
            if (row >= N) break;
            ulonglong2 w0, w1;
            w0.x = add2(acc2[i][0], bpk[0]);
            w0.y = add2(acc2[i][1], bpk[1]);
            w1.x = add2(acc2[i][2], bpk[2]);
            w1.y = add2(acc2[i][3], bpk[3]);
            *(ulonglong2*)(g_skip + (size_t)row * HF_ + tx * 8) = w0;
            *(ulonglong2*)(g_skip + (size_t)row * HF_ + tx * 8 + 4) = w1;
        }
    }
}

// ---------------- K2: per-edge scores, float4 smem table ---------------------
__global__ __launch_bounds__(1024) void k2_edge_scores(
    const int* __restrict__ ei, const float* __restrict__ edges,
    const int* __restrict__ bids, int E)
{
    extern __shared__ float4 s_w4[];   // [64][65] float4
    int t = threadIdx.x;

    {
        const float4* g4 = (const float4*)g_waet;
        for (int i = t; i < EDGED_ * BMAX_; i += 1024) {
            int p = i >> 6, b = i & 63;
            s_w4[p * WAE_PADROW + b] = g4[i];
        }
    }
    __syncthreads();

    int lane = t & 31;
    int j = lane & 7;
    int esub = lane >> 3;
    int gw = (blockIdx.x * 1024 + t) >> 5;
    int nwarps = gridDim.x * 32;
    int G = (E + 3) >> 2;

    float m = -3.402823e38f;

    for (int g = gw; g < G; g += nwarps) {
        int e = g * 4 + esub;
        bool eok = e < E;
        int ec = eok ? e : E - 1;
        int b = bids[ec];

        const float4* er = (const float4*)(edges + (size_t)ec * EDGED_ + j * 8);
        float4 q0 = er[0], q1 = er[1];
        float ev[8] = {q0.x, q0.y, q0.z, q0.w, q1.x, q1.y, q1.z, q1.w};

        const float4* wp = s_w4 + j * WAE_PADROW + b;   // p = dd*8 + j
        float a0 = 0.f, a1 = 0.f, a2 = 0.f, a3 = 0.f;
        #pragma unroll
        for (int dd = 0; dd < 8; dd++) {
            float4 w = wp[dd * (8 * WAE_PADROW)];
            float evv = ev[dd];
            a0 += evv * w.x;
            a1 += evv * w.y;
            a2 += evv * w.z;
            a3 += evv * w.w;
        }
        #pragma unroll
        for (int mask = 1; mask <= 4; mask <<= 1) {
            a0 += __shfl_xor_sync(~0u, a0, mask);
            a1 += __shfl_xor_sync(~0u, a1, mask);
            a2 += __shfl_xor_sync(~0u, a2, mask);
            a3 += __shfl_xor_sync(~0u, a3, mask);
        }
        if (j == 0 && eok) {
            int src = ei[e], trg = ei[E + e];
            float4 sv = *(const float4*)(g_ss + src * H_);
            float4 tv = *(const float4*)(g_st + trg * H_);
            float4 s = make_float4(a0 + sv.x + tv.x, a1 + sv.y + tv.y,
                                   a2 + sv.z + tv.z, a3 + sv.w + tv.w);
            s.x = s.x > 0.f ? s.x : 0.2f * s.x;
            s.y = s.y > 0.f ? s.y : 0.2f * s.y;
            s.z = s.z > 0.f ? s.z : 0.2f * s.z;
            s.w = s.w > 0.f ? s.w : 0.2f * s.w;
            *((float4*)g_scores + e) = s;
            m = fmaxf(m, fmaxf(fmaxf(s.x, s.y), fmaxf(s.z, s.w)));
        }
    }

    __shared__ float wm[32];
    #pragma unroll
    for (int mask = 16; mask >= 1; mask >>= 1) m = fmaxf(m, __shfl_xor_sync(~0u, m, mask));
    if ((t & 31) == 0) wm[t >> 5] = m;
    __syncthreads();
    if (t < 32) {
        float v = wm[t];
        #pragma unroll
        for (int mask = 16; mask >= 1; mask >>= 1) v = fmaxf(v, __shfl_xor_sync(~0u, v, mask));
        if (t == 0) atomicMax(&g_gmax, encf(v));
    }
}

// ---------------- K3a: elementwise exp(score - max) --------------------------
__global__ void k3a_exp(int E) {
    int e = blockIdx.x * blockDim.x + threadIdx.x;
    if (e >= E) return;
    float gm = decf(g_gmax);
    float4 s = *((float4*)g_scores + e);
    float4 ex = make_float4(expf(s.x - gm), expf(s.y - gm), expf(s.z - gm), expf(s.w - gm));
    *((float4*)g_scores + e) = ex;
}

// ---------------- K3b: fused dual-direction gather + LayerNorm ---------------
__device__ __forceinline__ void gat_dir(const int2* __restrict__ csr,
                                        const int* __restrict__ off,
                                        int n, int lane, int h,
                                        float4& sum, float& den)
{
    int beg = off[n], end = off[n + 1];
    sum = make_float4(0.f, 0.f, 0.f, 0.f);
    den = 0.f;
    int2 c = make_int2(0, 0);
    if (beg < end) c = csr[beg];
    for (int k = beg; k < end; k++) {
        float w = g_scores[c.x * H_ + h];
        float4 p = *((const float4*)g_proj + (size_t)c.y * 32 + lane);
        int kn = k + 1;
        int2 cn = c;
        if (kn < end) cn = csr[kn];
        den += w;
        sum.x += w * p.x; sum.y += w * p.y;
        sum.z += w * p.z; sum.w += w * p.w;
        c = cn;
    }
}

__global__ __launch_bounds__(256) void k3b_fused(
    const float* __restrict__ gamma, const float* __restrict__ beta,
    float* __restrict__ out, int N)
{
    int n = (int)((blockIdx.x * 256 + threadIdx.x) >> 5);
    int lane = threadIdx.x & 31;
    if (n >= N) return;
    int h = lane >> 3;

    float4 skip = *((const float4*)g_skip + (size_t)n * 32 + lane);

    // src_feats: aggregated at src, lifts proj[trg] (other stored in csr)
    float4 ssum; float sden;
    gat_dir(g_csr_src, g_off_src, n, lane, h, ssum, sden);
    float sinv = 1.f / (sden + 1e-16f);
    float4 a = make_float4(skip.x + ssum.x * sinv, skip.y + ssum.y * sinv,
                           skip.z + ssum.z * sinv, skip.w + ssum.w * sinv);

    // trg_feats: aggregated at trg, lifts proj[src]
    float4 tsum; float tden;
    gat_dir(g_csr_trg, g_off_trg, n, lane, h, tsum, tden);
    float tinv = 1.f / (tden + 1e-16f);
    float4 b = make_float4(skip.x + tsum.x * tinv, skip.y + tsum.y * tinv,
                           skip.z + tsum.z * tinv, skip.w + tsum.w * tinv);

    // LayerNorm over concat([src_feats, trg_feats]) = 256 values
    float s = a.x + a.y + a.z + a.w + b.x + b.y + b.z + b.w;
    float q = a.x * a.x + a.y * a.y + a.z * a.z + a.w * a.w +
              b.x * b.x + b.y * b.y + b.z * b.z + b.w * b.w;
    #pragma unroll
    for (int mask = 16; mask >= 1; mask >>= 1) {
        s += __shfl_xor_sync(~0u, s, mask);
        q += __shfl_xor_sync(~0u, q, mask);
    }
    float mu = s * (1.f / 256.f);
    float var = q * (1.f / 256.f) - mu * mu;
    float r = rsqrtf(var + 1e-5f);
    float4 g1 = ((const float4*)gamma)[lane];
    float4 be1 = ((const float4*)beta)[lane];
    float4 g2 = ((const float4*)gamma)[32 + lane];
    float4 be2 = ((const float4*)beta)[32 + lane];
    float4 o1 = make_float4((a.x - mu) * r * g1.x + be1.x, (a.y - mu) * r * g1.y + be1.y,
                            (a.z - mu) * r * g1.z + be1.z, (a.w - mu) * r * g1.w + be1.w);
    float4 o2 = make_float4((b.x - mu) * r * g2.x + be2.x, (b.y - mu) * r * g2.y + be2.y,
                            (b.z - mu) * r * g2.z + be2.z, (b.w - mu) * r * g2.w + be2.w);
    ((float4*)out)[(size_t)n * 64 + lane] = o1;
    ((float4*)out)[(size_t)n * 64 + 32 + lane] = o2;
}

// ---------------------------------------------------------------------------
static inline int cdiv(int a, int b) { return (a + b - 1) / b; }

extern "C" void kernel_launch(void* const* d_in, const int* in_sizes, int n_in,
                              void* d_out, int out_size)
{
    const float* x      = (const float*)d_in[0];
    const int*   ei     = (const int*)d_in[1];
    const float* edges  = (const float*)d_in[2];
    const float* ins    = (const float*)d_in[3];
    const int*   bids   = (const int*)d_in[4];
    const float* Wp     = (const float*)d_in[6];
    const float* We     = (const float*)d_in[7];
    const float* Wsi    = (const float*)d_in[8];
    const float* bsi    = (const float*)d_in[9];
    const float* Wti    = (const float*)d_in[10];
    const float* bti    = (const float*)d_in[11];
    const float* Wei    = (const float*)d_in[12];
    const float* bei    = (const float*)d_in[13];
    const float* a_src  = (const float*)d_in[14];
    const float* a_trg  = (const float*)d_in[15];
    const float* a_edge = (const float*)d_in[16];
    const float* bias   = (const float*)d_in[17];
    const float* Wsk    = (const float*)d_in[18];
    const float* gamma  = (const float*)d_in[19];
    const float* beta   = (const float*)d_in[20];

    int N = in_sizes[0] / FIN_;
    int E = in_sizes[2] / EDGED_;
    int B = in_sizes[3] / HID_;
    int mle = N / B;
    int nseg = cdiv(N, 256);

    const int k2_smem = EDGED_ * WAE_PADROW * (int)sizeof(float4);  // 66560 B
    cudaFuncSetAttribute(k2_edge_scores,
                         cudaFuncAttributeMaxDynamicSharedMemorySize, k2_smem);

    // CSR build (parallel 3-phase scan)
    k_init<<<cdiv(N, 256), 256>>>(N);
    k_hist<<<cdiv(E, 256), 256>>>(ei, E);
    {
        dim3 g1(nseg, 2);
        k_scanA<<<g1, 256>>>(N);
        k_scanB<<<1, 512>>>(nseg);
        k_scanC<<<g1, 256>>>(N);
    }
    k_fill<<<cdiv(E, 256), 256>>>(ei, E);

    k0_batch<<<B, 128>>>(ins, Wsi, bsi, Wti, bti, Wei, bei, a_src, a_trg, a_edge, We);
    {
        dim3 grid(cdiv(N, 128), 2);
        k1_gemm<<<grid, 256>>>(x, Wp, Wsk, bias, N, mle);
    }
    k2_edge_scores<<<296, 1024, k2_smem>>>(ei, edges, bids, E);
    k3a_exp<<<cdiv(E, 256), 256>>>(E);
    k3b_fused<<<cdiv(N * 32, 256), 256>>>(gamma, beta, (float*)d_out, N);
}